// round 15
// baseline (speedup 1.0000x reference)
#include <cuda.h>
#include <cuda_runtime.h>
#include <cuda_fp16.h>
#include <cstdint>

#define M_DIM 2048
#define N_DIM 4096
#define K_DIM 4096

// ---------------- scratch (static device globals; no runtime alloc) -------
__device__ __half g_Wh[(size_t)N_DIM * K_DIM];   // transcribed weight, fp16
__device__ __half g_Xh[(size_t)M_DIM * K_DIM];   // x, fp16
// split-K partials: 864 quarter tasks x (128x128) fp32 = 56.6MB
#define NSPLIT_TILES 216
#define NQTASK 864
__device__ float g_P[(size_t)NQTASK * 16384];
// per-split-tile completion counters, lane-sharded (bucket = tile*64 + lane)
#define QC_WORDS (NSPLIT_TILES * 64)
__device__ uint32_t g_qcnt[QC_WORDS];

// ---------------- PTX helpers ----------------------------------------------
__device__ __forceinline__ uint32_t smem_u32(const void* p) {
    uint32_t a;
    asm("{ .reg .u64 t; cvta.to.shared.u64 t, %1; cvt.u32.u64 %0, t; }" : "=r"(a) : "l"(p));
    return a;
}
#define MBAR_INIT(a, n) \
    asm volatile("mbarrier.init.shared.b64 [%0], %1;" :: "r"(a), "r"((uint32_t)(n)) : "memory")
#define MBAR_EXPECT_TX(a, b) \
    asm volatile("mbarrier.arrive.expect_tx.shared.b64 _, [%0], %1;" :: "r"(a), "r"((uint32_t)(b)) : "memory")
#define MBAR_ARRIVE(a) \
    asm volatile("mbarrier.arrive.shared.b64 _, [%0];" :: "r"(a) : "memory")
#define MBAR_WAIT(a, ph) do {                                                   \
    uint32_t _m = (a); uint32_t _p = (ph); uint32_t _d;                         \
    asm volatile("{\n\t.reg .pred p;\n\t"                                       \
        "mbarrier.try_wait.parity.acquire.cta.shared::cta.b64 p, [%1], %2;\n\t" \
        "selp.b32 %0, 1, 0, p;\n\t}"                                            \
        : "=r"(_d) : "r"(_m), "r"(_p) : "memory");                              \
    if (!_d) {                                                                  \
        asm volatile("{\n\t.reg .pred P1;\n\t"                                  \
            "WL_%=:\n\t"                                                        \
            "mbarrier.try_wait.parity.acquire.cta.shared::cta.b64 P1, [%0], %1, 0x989680;\n\t" \
            "@P1 bra.uni WD_%=;\n\t"                                            \
            "bra.uni WL_%=;\n\t"                                                \
            "WD_%=:\n\t}" :: "r"(_m), "r"(_p) : "memory");                      \
    } } while (0)
#define TMA_LOAD_3D(smem_addr, map, cx, cy, cz, bar)                            \
    asm volatile("cp.async.bulk.tensor.3d.shared::cta.global.tile"              \
        ".mbarrier::complete_tx::bytes "                                        \
        "[%0], [%1, {%2, %3, %4}], [%5];"                                       \
        :: "r"((uint32_t)(smem_addr)), "l"(map),                                \
           "r"((int32_t)(cx)), "r"((int32_t)(cy)), "r"((int32_t)(cz)),          \
           "r"((uint32_t)(bar)) : "memory")

__device__ __forceinline__ void ldsm_x4(uint32_t (&r)[4], uint32_t addr) {
    asm volatile("ldmatrix.sync.aligned.m8n8.x4.shared.b16 {%0,%1,%2,%3}, [%4];"
        : "=r"(r[0]), "=r"(r[1]), "=r"(r[2]), "=r"(r[3]) : "r"(addr));
}
__device__ __forceinline__ void mma16816(float (&d)[4], const uint32_t (&a)[4],
                                         uint32_t b0, uint32_t b1) {
    asm volatile("mma.sync.aligned.m16n8k16.row.col.f32.f16.f16.f32 "
        "{%0,%1,%2,%3},{%4,%5,%6,%7},{%8,%9},{%0,%1,%2,%3};"
        : "+f"(d[0]), "+f"(d[1]), "+f"(d[2]), "+f"(d[3])
        : "r"(a[0]), "r"(a[1]), "r"(a[2]), "r"(a[3]), "r"(b0), "r"(b1));
}

// FMA-pipe-only sin: range-reduce by pi via magic-number rounding (no CVT,
// no MUFU), odd Taylor to y^9 on [-pi/2, pi/2]. |err| < 4e-6.
#define SIN_MAGIC 12582912.0f      // 1.5 * 2^23
#define SIN_INVPI 0.318309886f
#define SIN_PIHI  3.14159274f      // fp32(pi)
#define SIN_PILO  -8.742278e-8f    // pi - fp32(pi)
__device__ __forceinline__ float sin_poly(float x) {
    const float t  = fmaf(x, SIN_INVPI, SIN_MAGIC);
    const int  par = (__float_as_int(t) & 1) << 31;   // parity of nearest n
    const float nf = t - SIN_MAGIC;                    // rint(x/pi)
    float y = fmaf(nf, -SIN_PIHI, x);
    y = fmaf(nf, -SIN_PILO, y);
    const float z = y * y;
    float r = fmaf(2.75573192e-6f, z, -1.98412698e-4f);
    r = fmaf(r, z, 8.33333333e-3f);
    r = fmaf(r, z, -1.66666667e-1f);
    const float s = fmaf(y * z, r, y);
    return __int_as_float(__float_as_int(s) ^ par);    // *(-1)^n
}

// ---------------------------------------------------------------------------
// Kernel 1: fractal transcription of W (fp16) + fp16 round of X + counter zero.
// ---------------------------------------------------------------------------
#define NW8 ((size_t)N_DIM * K_DIM / 8)           // 2,097,152 threads
#define NX8 ((size_t)M_DIM * K_DIM / 8)           // 1,048,576 threads
#define PREP_BLOCKS ((unsigned)((NW8 + NX8 + QC_WORDS) / 256))   // 12342 exactly

__global__ void prep_k(const float* __restrict__ x, const float* __restrict__ seed,
                       const float* __restrict__ da, const float* __restrict__ db,
                       int niter) {
    __shared__ float sa[32], sb[32];
    if (threadIdx.x < 32 && threadIdx.x < niter) {
        sa[threadIdx.x] = da[threadIdx.x];
        sb[threadIdx.x] = db[threadIdx.x];
    }
    __syncthreads();

    size_t gid = (size_t)blockIdx.x * blockDim.x + threadIdx.x;
    if (gid < NW8) {
        size_t i = gid * 8;
        float4 w0 = *reinterpret_cast<const float4*>(seed + i);
        float4 w1 = *reinterpret_cast<const float4*>(seed + i + 4);
        float v0 = w0.x, v1 = w0.y, v2 = w0.z, v3 = w0.w;
        float v4 = w1.x, v5 = w1.y, v6 = w1.z, v7 = w1.w;
        #pragma unroll 20
        for (int k = 0; k < niter; k++) {
            const float a = sa[k], b = sb[k];
            v0 = fmaf(b, sin_poly(v0), a * v0);    // FMA pipe
            v1 = fmaf(b, __sinf(v1), a * v1);      // MUFU
            v2 = fmaf(b, __sinf(v2), a * v2);
            v3 = fmaf(b, __sinf(v3), a * v3);
            v4 = fmaf(b, __sinf(v4), a * v4);
            v5 = fmaf(b, __sinf(v5), a * v5);
            v6 = fmaf(b, __sinf(v6), a * v6);
            v7 = fmaf(b, __sinf(v7), a * v7);
        }
        __half2 h0 = __floats2half2_rn(v0, v1);
        __half2 h1 = __floats2half2_rn(v2, v3);
        __half2 h2 = __floats2half2_rn(v4, v5);
        __half2 h3 = __floats2half2_rn(v6, v7);
        uint4 o = make_uint4(*(uint32_t*)&h0, *(uint32_t*)&h1,
                             *(uint32_t*)&h2, *(uint32_t*)&h3);
        *reinterpret_cast<uint4*>(g_Wh + i) = o;
    } else if (gid < NW8 + NX8) {
        size_t i = (gid - NW8) * 8;
        float4 a0 = *reinterpret_cast<const float4*>(x + i);
        float4 a1 = *reinterpret_cast<const float4*>(x + i + 4);
        __half2 h0 = __floats2half2_rn(a0.x, a0.y);
        __half2 h1 = __floats2half2_rn(a0.z, a0.w);
        __half2 h2 = __floats2half2_rn(a1.x, a1.y);
        __half2 h3 = __floats2half2_rn(a1.z, a1.w);
        uint4 o = make_uint4(*(uint32_t*)&h0, *(uint32_t*)&h1,
                             *(uint32_t*)&h2, *(uint32_t*)&h3);
        *reinterpret_cast<uint4*>(g_Xh + i) = o;
    } else if (gid < NW8 + NX8 + QC_WORDS) {
        g_qcnt[gid - NW8 - NX8] = 0;     // replay-safe counter reset
    }
}

// ---------------------------------------------------------------------------
// Kernel 2: persistent GEMM + fused split-K reduce. 296 CTAs x 160 threads,
//   2 CTAs/SM. Task order per CTA: nq quarter-K tasks FIRST, then 1 full-K
//   tile. Quarter partials -> g_P + per-thread release into g_qcnt. The
//   producer warp of CTA bx<216 reduces split tile bx (4 partials + bias)
//   interleaved with TMA production of the full tile.
// ---------------------------------------------------------------------------
#define NSTAGES 3
#define BK      64
#define A_BYTES (128 * 128)                  // 16KB
#define STAGE_BYTES (2 * A_BYTES)            // 32KB
#define DYN_SMEM (NSTAGES * STAGE_BYTES + 1024)   // 99328B -> 2 CTAs/SM
#define NCTA    296

__device__ __forceinline__ void task_decode(int bx, int nq, int tt,
                                            int& tm, int& tn,
                                            int& kb, int& nch, int& j) {
    if (tt < nq) {
        j = bx + tt * NCTA;                        // 0..863
        const int tile = NCTA + (j % NSPLIT_TILES);
        tm = (tile & 15) << 7;
        tn = (tile >> 4) << 7;
        kb = (j / NSPLIT_TILES) * 16;              // k-quarter
        nch = 16;
    } else {
        tm = (bx & 15) << 7;
        tn = (bx >> 4) << 7;
        kb = 0; nch = 64; j = -1;
    }
}

__device__ __forceinline__ void reduce_elem(int e, int rt, int rtm, int rtn,
                                            const float* __restrict__ bias,
                                            float* __restrict__ out) {
    const int row = rtm + (e >> 5);
    const int c4 = e & 31;
    const float4 a = *(reinterpret_cast<const float4*>(g_P + ((size_t)(0 * NSPLIT_TILES + rt) << 14)) + e);
    const float4 b = *(reinterpret_cast<const float4*>(g_P + ((size_t)(1 * NSPLIT_TILES + rt) << 14)) + e);
    const float4 c = *(reinterpret_cast<const float4*>(g_P + ((size_t)(2 * NSPLIT_TILES + rt) << 14)) + e);
    const float4 d = *(reinterpret_cast<const float4*>(g_P + ((size_t)(3 * NSPLIT_TILES + rt) << 14)) + e);
    const float4 bv = __ldg(reinterpret_cast<const float4*>(bias) + rtn / 4 + c4);
    float4 r;
    r.x = (a.x + b.x) + (c.x + d.x) + bv.x;
    r.y = (a.y + b.y) + (c.y + d.y) + bv.y;
    r.z = (a.z + b.z) + (c.z + d.z) + bv.z;
    r.w = (a.w + b.w) + (c.w + d.w) + bv.w;
    reinterpret_cast<float4*>(out)[(size_t)row * (N_DIM / 4) + rtn / 4 + c4] = r;
}

__global__ void __launch_bounds__(160, 2)
gemm_k(const __grid_constant__ CUtensorMap tma_a,
       const __grid_constant__ CUtensorMap tma_b,
       const float* __restrict__ bias, float* __restrict__ out) {
    extern __shared__ char dsm[];
    __shared__ uint64_t bars[2 * NSTAGES];

    const uint32_t tiles_s = (smem_u32(dsm) + 1023u) & ~1023u;
    const uint32_t bar0 = smem_u32(bars);
    const int tid = threadIdx.x;
    const int wid = tid >> 5;
    const int lane = tid & 31;
    const int bx = blockIdx.x;
    const int nq = (bx < NQTASK - 2 * NCTA) ? 3 : 2;   // bx<272 -> 3 : 2
    const int ntask = nq + 1;

    if (tid == 0) {
        #pragma unroll
        for (int s = 0; s < NSTAGES; s++) {
            MBAR_INIT(bar0 + s * 8, 1);               // full: tx-based
            MBAR_INIT(bar0 + (NSTAGES + s) * 8, 4);   // empty: 4 MMA warps
        }
    }
    __syncthreads();

    // ========== producer warp (4): TMA (lane 0) + fused reduce (all lanes) ==
    if (wid == 4) {
        const bool has_red = (bx < NSPLIT_TILES);
        const int rt = bx;
        const int rtile = NCTA + rt;
        const int rtm = (rtile & 15) << 7;
        const int rtn = (rtile >> 4) << 7;
        bool red_ready = false;
        int red_pos = 0;                 // of 128 float4 per lane

        int g = 0;
        for (int tt = 0; tt < ntask; tt++) {
            int tm, tn, kb, nch, j;
            task_decode(bx, nq, tt, tm, tn, kb, nch, j);
            for (int t = 0; t < nch; t++, g++) {
                const int s = g % NSTAGES;
                if (g >= NSTAGES)
                    MBAR_WAIT(bar0 + (NSTAGES + s) * 8, ((g / NSTAGES) - 1) & 1);
                if (lane == 0) {
                    MBAR_EXPECT_TX(bar0 + s * 8, STAGE_BYTES);
                    const uint32_t st = tiles_s + s * STAGE_BYTES;
                    const int cx = (kb + t) * BK;
                    TMA_LOAD_3D(st,           &tma_a, cx, tm, 0, bar0 + s * 8);
                    TMA_LOAD_3D(st + A_BYTES, &tma_b, cx, tn, 0, bar0 + s * 8);
                }
                // opportunistic fused reduce (hidden under tensor work)
                if (has_red && red_pos < 128) {
                    if (!red_ready) {
                        uint32_t v;
                        asm volatile("ld.relaxed.gpu.global.u32 %0, [%1];"
                                     : "=r"(v) : "l"(g_qcnt + rt * 64 + lane) : "memory");
                        if (__all_sync(0xffffffffu, v >= 16)) {
                            asm volatile("ld.acquire.gpu.global.u32 %0, [%1];"
                                         : "=r"(v) : "l"(g_qcnt + rt * 64 + lane) : "memory");
                            __syncwarp();
                            red_ready = true;
                        }
                    }
                    if (red_ready) {
                        int end = red_pos + 8;
                        if (end > 128) end = 128;
                        for (; red_pos < end; red_pos++)
                            reduce_elem(red_pos * 32 + lane, rt, rtm, rtn, bias, out);
                    }
                }
            }
        }
        // finish any leftover reduce work (blocking)
        if (has_red && red_pos < 128) {
            if (!red_ready) {
                uint32_t v; int ok;
                do {
                    asm volatile("ld.acquire.gpu.global.u32 %0, [%1];"
                                 : "=r"(v) : "l"(g_qcnt + rt * 64 + lane) : "memory");
                    ok = (v >= 16);
                    if (!__all_sync(0xffffffffu, ok))
                        asm volatile("nanosleep.u32 256;");
                    else break;
                } while (true);
                __syncwarp();
            }
            for (; red_pos < 128; red_pos++)
                reduce_elem(red_pos * 32 + lane, rt, rtm, rtn, bias, out);
        }
        return;
    }

    // ===================== MMA warps (0..3), warp tile 64x64 =====
    const int wm = (wid & 1) * 64;       // {0,64}
    const int wn = (wid >> 1) * 64;      // {0,64}

    const int a_row_l = (lane & 15);
    const int a_k16   = (lane >> 4) * 16;
    const int b_row_l = (lane & 7) + ((lane >> 4) << 3);
    const int b_k16   = ((lane >> 3) & 1) * 16;

    uint32_t a_base[4], a_xor[4];
    #pragma unroll
    for (int fm = 0; fm < 4; fm++) {
        const int r = wm + fm * 16 + a_row_l;
        a_base[fm] = r * 128;
        a_xor[fm] = (r & 7) << 4;
    }
    uint32_t b_base[4], b_xor[4];
    #pragma unroll
    for (int fn = 0; fn < 4; fn++) {
        const int r = wn + fn * 16 + b_row_l;
        b_base[fn] = r * 128;
        b_xor[fn] = (r & 7) << 4;
    }

    int g = 0;
    for (int tt = 0; tt < ntask; tt++) {
        int tm, tn, kb, nch, j;
        task_decode(bx, nq, tt, tm, tn, kb, nch, j);

        float acc[4][8][4];
        #pragma unroll
        for (int i = 0; i < 4; i++)
            #pragma unroll
            for (int jj = 0; jj < 8; jj++)
                #pragma unroll
                for (int c = 0; c < 4; c++) acc[i][jj][c] = 0.f;

        for (int t = 0; t < nch; t++, g++) {
            const int s = g % NSTAGES;
            MBAR_WAIT(bar0 + s * 8, (g / NSTAGES) & 1);
            const uint32_t sa = tiles_s + s * STAGE_BYTES;
            const uint32_t sb = sa + A_BYTES;

            #pragma unroll
            for (int ks = 0; ks < 4; ks++) {
                uint32_t af[4][4], bf[4][4];
                #pragma unroll
                for (int fm = 0; fm < 4; fm++)
                    ldsm_x4(af[fm], sa + a_base[fm] + ((ks * 32 + a_k16) ^ a_xor[fm]));
                #pragma unroll
                for (int fn = 0; fn < 4; fn++)
                    ldsm_x4(bf[fn], sb + b_base[fn] + ((ks * 32 + b_k16) ^ b_xor[fn]));
                #pragma unroll
                for (int fm = 0; fm < 4; fm++)
                    #pragma unroll
                    for (int fn = 0; fn < 4; fn++) {
                        mma16816(acc[fm][2 * fn],     af[fm], bf[fn][0], bf[fn][1]);
                        mma16816(acc[fm][2 * fn + 1], af[fm], bf[fn][2], bf[fn][3]);
                    }
            }
            __syncwarp();
            if (lane == 0) MBAR_ARRIVE(bar0 + (NSTAGES + s) * 8);
        }

        // ---- epilogue ----
        const int gid4 = lane >> 2;
        const int tig  = lane & 3;
        if (j < 0) {
            #pragma unroll
            for (int fm = 0; fm < 4; fm++) {
                const int row = tm + wm + fm * 16 + gid4;
                #pragma unroll
                for (int fn = 0; fn < 8; fn++) {
                    const int col = tn + wn + fn * 8 + tig * 2;
                    const float b0 = __ldg(&bias[col]);
                    const float b1 = __ldg(&bias[col + 1]);
                    float2 v0 = make_float2(acc[fm][fn][0] + b0, acc[fm][fn][1] + b1);
                    float2 v1 = make_float2(acc[fm][fn][2] + b0, acc[fm][fn][3] + b1);
                    *reinterpret_cast<float2*>(out + (size_t)row * N_DIM + col)       = v0;
                    *reinterpret_cast<float2*>(out + (size_t)(row + 8) * N_DIM + col) = v1;
                }
            }
        } else {
            // quarter-K partial: plain STG into scratch, then per-thread
            // release into the tile's lane-sharded counter (R8 pattern).
            float* base = g_P + (size_t)j * 16384;
            #pragma unroll
            for (int fm = 0; fm < 4; fm++) {
                const int rl2 = wm + fm * 16 + gid4;
                #pragma unroll
                for (int fn = 0; fn < 8; fn++) {
                    const int cl = wn + fn * 8 + tig * 2;
                    *reinterpret_cast<float2*>(base + rl2 * 128 + cl) =
                        make_float2(acc[fm][fn][0], acc[fm][fn][1]);
                    *reinterpret_cast<float2*>(base + (rl2 + 8) * 128 + cl) =
                        make_float2(acc[fm][fn][2], acc[fm][fn][3]);
                }
            }
            asm volatile("red.release.gpu.global.add.u32 [%0], %1;"
                         :: "l"(g_qcnt + (j % NSPLIT_TILES) * 64 + lane), "r"(1u)
                         : "memory");
        }
    }
}

// ---------------------------------------------------------------------------
typedef CUresult (*tmap_fn)(CUtensorMap*, CUtensorMapDataType, cuuint32_t, void*,
                            const cuuint64_t*, const cuuint64_t*, const cuuint32_t*,
                            const cuuint32_t*, CUtensorMapInterleave, CUtensorMapSwizzle,
                            CUtensorMapL2promotion, CUtensorMapFloatOOBfill);

static void make_map(tmap_fn enc, CUtensorMap* m, void* base, uint64_t rows) {
    cuuint64_t dims[3]    = {K_DIM, rows, 1};
    cuuint64_t strides[2] = {K_DIM * 2ull, rows * K_DIM * 2ull};
    cuuint32_t box[3]     = {64, 128, 1};    // 64 halves = 128B row (SW128)
    cuuint32_t es[3]      = {1, 1, 1};
    enc(m, CU_TENSOR_MAP_DATA_TYPE_FLOAT16, 3, base, dims, strides, box, es,
        CU_TENSOR_MAP_INTERLEAVE_NONE, CU_TENSOR_MAP_SWIZZLE_128B,
        CU_TENSOR_MAP_L2_PROMOTION_L2_128B, CU_TENSOR_MAP_FLOAT_OOB_FILL_NONE);
}

extern "C" void kernel_launch(void* const* d_in, const int* in_sizes, int n_in,
                              void* d_out, int out_size) {
    const float* x    = (const float*)d_in[0];   // [2048, 4096]
    const float* seed = (const float*)d_in[1];   // [4096, 4096]
    const float* da   = (const float*)d_in[2];   // [20]
    const float* db   = (const float*)d_in[3];   // [20]
    const float* bias = (const float*)d_in[4];   // [4096]
    float* out = (float*)d_out;                  // [2048, 4096]
    const int niter = in_sizes[2];

    void* pW = nullptr; void* pX = nullptr;
    cudaGetSymbolAddress(&pW, g_Wh);
    cudaGetSymbolAddress(&pX, g_Xh);

    tmap_fn enc = nullptr;
    cudaDriverEntryPointQueryResult qr;
    cudaGetDriverEntryPointByVersion("cuTensorMapEncodeTiled", (void**)&enc, 12000,
                                     cudaEnableDefault, &qr);

    CUtensorMap map_a, map_b;
    make_map(enc, &map_a, pX, M_DIM);   // A = X
    make_map(enc, &map_b, pW, N_DIM);   // B = W

    prep_k<<<PREP_BLOCKS, 256>>>(x, seed, da, db, niter);

    cudaFuncSetAttribute(gemm_k, cudaFuncAttributeMaxDynamicSharedMemorySize, DYN_SMEM);
    gemm_k<<<NCTA, 160, DYN_SMEM>>>(map_a, map_b, bias, out);
}

// round 16
// speedup vs baseline: 1.0561x; 1.0561x over previous
#include <cuda.h>
#include <cuda_runtime.h>
#include <cuda_fp16.h>
#include <cstdint>

#define M_DIM 2048
#define N_DIM 4096
#define K_DIM 4096

// ---------------- scratch (static device globals; no runtime alloc) -------
__device__ __half g_Wh[(size_t)N_DIM * K_DIM];   // transcribed weight, fp16
__device__ __half g_Xh[(size_t)M_DIM * K_DIM];   // x, fp16
// split-K partials: 864 quarter tasks x (128x128) fp32 = 56.6MB
#define NSPLIT_TILES 216
#define NQTASK 864
__device__ float g_P[(size_t)NQTASK * 16384];
// per-split-tile completion counters, lane-sharded (word = tile*64 + lane,
// lanes 0..31 used; each word reaches 16 = 4 warps x 4 quarters)
#define QC_WORDS (NSPLIT_TILES * 64)
__device__ uint32_t g_qcnt[QC_WORDS];

// ---------------- PTX helpers ----------------------------------------------
__device__ __forceinline__ uint32_t smem_u32(const void* p) {
    uint32_t a;
    asm("{ .reg .u64 t; cvta.to.shared.u64 t, %1; cvt.u32.u64 %0, t; }" : "=r"(a) : "l"(p));
    return a;
}
#define MBAR_INIT(a, n) \
    asm volatile("mbarrier.init.shared.b64 [%0], %1;" :: "r"(a), "r"((uint32_t)(n)) : "memory")
#define MBAR_EXPECT_TX(a, b) \
    asm volatile("mbarrier.arrive.expect_tx.shared.b64 _, [%0], %1;" :: "r"(a), "r"((uint32_t)(b)) : "memory")
#define MBAR_ARRIVE(a) \
    asm volatile("mbarrier.arrive.shared.b64 _, [%0];" :: "r"(a) : "memory")
#define MBAR_WAIT(a, ph) do {                                                   \
    uint32_t _m = (a); uint32_t _p = (ph); uint32_t _d;                         \
    asm volatile("{\n\t.reg .pred p;\n\t"                                       \
        "mbarrier.try_wait.parity.acquire.cta.shared::cta.b64 p, [%1], %2;\n\t" \
        "selp.b32 %0, 1, 0, p;\n\t}"                                            \
        : "=r"(_d) : "r"(_m), "r"(_p) : "memory");                              \
    if (!_d) {                                                                  \
        asm volatile("{\n\t.reg .pred P1;\n\t"                                  \
            "WL_%=:\n\t"                                                        \
            "mbarrier.try_wait.parity.acquire.cta.shared::cta.b64 P1, [%0], %1, 0x989680;\n\t" \
            "@P1 bra.uni WD_%=;\n\t"                                            \
            "bra.uni WL_%=;\n\t"                                                \
            "WD_%=:\n\t}" :: "r"(_m), "r"(_p) : "memory");                      \
    } } while (0)
#define TMA_LOAD_3D(smem_addr, map, cx, cy, cz, bar)                            \
    asm volatile("cp.async.bulk.tensor.3d.shared::cta.global.tile"              \
        ".mbarrier::complete_tx::bytes "                                        \
        "[%0], [%1, {%2, %3, %4}], [%5];"                                       \
        :: "r"((uint32_t)(smem_addr)), "l"(map),                                \
           "r"((int32_t)(cx)), "r"((int32_t)(cy)), "r"((int32_t)(cz)),          \
           "r"((uint32_t)(bar)) : "memory")

__device__ __forceinline__ void ldsm_x4(uint32_t (&r)[4], uint32_t addr) {
    asm volatile("ldmatrix.sync.aligned.m8n8.x4.shared.b16 {%0,%1,%2,%3}, [%4];"
        : "=r"(r[0]), "=r"(r[1]), "=r"(r[2]), "=r"(r[3]) : "r"(addr));
}
__device__ __forceinline__ void mma16816(float (&d)[4], const uint32_t (&a)[4],
                                         uint32_t b0, uint32_t b1) {
    asm volatile("mma.sync.aligned.m16n8k16.row.col.f32.f16.f16.f32 "
        "{%0,%1,%2,%3},{%4,%5,%6,%7},{%8,%9},{%0,%1,%2,%3};"
        : "+f"(d[0]), "+f"(d[1]), "+f"(d[2]), "+f"(d[3])
        : "r"(a[0]), "r"(a[1]), "r"(a[2]), "r"(a[3]), "r"(b0), "r"(b1));
}

// FMA-pipe-only sin (validated R14): magic-number pi reduction + odd Taylor.
#define SIN_MAGIC 12582912.0f
#define SIN_INVPI 0.318309886f
#define SIN_PIHI  3.14159274f
#define SIN_PILO  -8.742278e-8f
__device__ __forceinline__ float sin_poly(float x) {
    const float t  = fmaf(x, SIN_INVPI, SIN_MAGIC);
    const int  par = (__float_as_int(t) & 1) << 31;
    const float nf = t - SIN_MAGIC;
    float y = fmaf(nf, -SIN_PIHI, x);
    y = fmaf(nf, -SIN_PILO, y);
    const float z = y * y;
    float r = fmaf(2.75573192e-6f, z, -1.98412698e-4f);
    r = fmaf(r, z, 8.33333333e-3f);
    r = fmaf(r, z, -1.66666667e-1f);
    const float s = fmaf(y * z, r, y);
    return __int_as_float(__float_as_int(s) ^ par);
}

// ---------------------------------------------------------------------------
// Kernel 1: fractal transcription of W (fp16) + fp16 round of X + counter zero.
// ---------------------------------------------------------------------------
#define NW8 ((size_t)N_DIM * K_DIM / 8)
#define NX8 ((size_t)M_DIM * K_DIM / 8)
#define PREP_BLOCKS ((unsigned)((NW8 + NX8 + QC_WORDS) / 256))

__global__ void prep_k(const float* __restrict__ x, const float* __restrict__ seed,
                       const float* __restrict__ da, const float* __restrict__ db,
                       int niter) {
    __shared__ float sa[32], sb[32];
    if (threadIdx.x < 32 && threadIdx.x < niter) {
        sa[threadIdx.x] = da[threadIdx.x];
        sb[threadIdx.x] = db[threadIdx.x];
    }
    __syncthreads();

    size_t gid = (size_t)blockIdx.x * blockDim.x + threadIdx.x;
    if (gid < NW8) {
        size_t i = gid * 8;
        float4 w0 = *reinterpret_cast<const float4*>(seed + i);
        float4 w1 = *reinterpret_cast<const float4*>(seed + i + 4);
        float v0 = w0.x, v1 = w0.y, v2 = w0.z, v3 = w0.w;
        float v4 = w1.x, v5 = w1.y, v6 = w1.z, v7 = w1.w;
        #pragma unroll 20
        for (int k = 0; k < niter; k++) {
            const float a = sa[k], b = sb[k];
            v0 = fmaf(b, sin_poly(v0), a * v0);    // FMA pipe
            v1 = fmaf(b, __sinf(v1), a * v1);      // MUFU
            v2 = fmaf(b, __sinf(v2), a * v2);
            v3 = fmaf(b, __sinf(v3), a * v3);
            v4 = fmaf(b, __sinf(v4), a * v4);
            v5 = fmaf(b, __sinf(v5), a * v5);
            v6 = fmaf(b, __sinf(v6), a * v6);
            v7 = fmaf(b, __sinf(v7), a * v7);
        }
        __half2 h0 = __floats2half2_rn(v0, v1);
        __half2 h1 = __floats2half2_rn(v2, v3);
        __half2 h2 = __floats2half2_rn(v4, v5);
        __half2 h3 = __floats2half2_rn(v6, v7);
        uint4 o = make_uint4(*(uint32_t*)&h0, *(uint32_t*)&h1,
                             *(uint32_t*)&h2, *(uint32_t*)&h3);
        *reinterpret_cast<uint4*>(g_Wh + i) = o;
    } else if (gid < NW8 + NX8) {
        size_t i = (gid - NW8) * 8;
        float4 a0 = *reinterpret_cast<const float4*>(x + i);
        float4 a1 = *reinterpret_cast<const float4*>(x + i + 4);
        __half2 h0 = __floats2half2_rn(a0.x, a0.y);
        __half2 h1 = __floats2half2_rn(a0.z, a0.w);
        __half2 h2 = __floats2half2_rn(a1.x, a1.y);
        __half2 h3 = __floats2half2_rn(a1.z, a1.w);
        uint4 o = make_uint4(*(uint32_t*)&h0, *(uint32_t*)&h1,
                             *(uint32_t*)&h2, *(uint32_t*)&h3);
        *reinterpret_cast<uint4*>(g_Xh + i) = o;
    } else if (gid < NW8 + NX8 + QC_WORDS) {
        g_qcnt[gid - NW8 - NX8] = 0;     // replay-safe counter reset
    }
}

// ---------------------------------------------------------------------------
// Kernel 2: persistent GEMM + TAIL split-K reduce. 296 CTAs x 160 threads,
//   2 CTAs/SM, 128x128 tile, 4 MMA warps + 1 pure-TMA producer (R14 engine).
//   Task order: nq quarter-K tasks FIRST, then the full-K tile. Quarter
//   partials -> g_P + per-thread release into g_qcnt. After the main loop,
//   each CTA reduces a static slice of the 216 split tiles (weighted: the 24
//   short-schedule CTAs take 2 whole tiles inside their slack).
// ---------------------------------------------------------------------------
#define NSTAGES 3
#define BK      64
#define A_BYTES (128 * 128)                  // 16KB
#define STAGE_BYTES (2 * A_BYTES)            // 32KB
#define DYN_SMEM (NSTAGES * STAGE_BYTES + 1024)   // 99328B -> 2 CTAs/SM
#define NCTA    296
#define NFAST   24                           // CTAs 272..295 (nq=2)
#define FAST_T0 168                          // they own tiles 168..215 (2 each)
#define SLOW_F4 2531                         // ceil(168*4096 / 272)

__device__ __forceinline__ void task_decode(int bx, int nq, int tt,
                                            int& tm, int& tn,
                                            int& kb, int& nch, int& j) {
    if (tt < nq) {
        j = bx + tt * NCTA;                        // 0..863
        const int tile = NCTA + (j % NSPLIT_TILES);
        tm = (tile & 15) << 7;
        tn = (tile >> 4) << 7;
        kb = (j / NSPLIT_TILES) * 16;              // k-quarter
        nch = 16;
    } else {
        tm = (bx & 15) << 7;
        tn = (bx >> 4) << 7;
        kb = 0; nch = 64; j = -1;
    }
}

__device__ __forceinline__ void reduce_elem(int u, const float* __restrict__ bias,
                                            float* __restrict__ out) {
    const int t = u >> 12;                 // split tile 0..215
    const int e = u & 4095;                // float4 within 128x128 tile
    const int tile = NCTA + t;
    const int tm = (tile & 15) << 7;
    const int tn = (tile >> 4) << 7;
    const int row = tm + (e >> 5);
    const int c4 = e & 31;
    const float4 a = *(reinterpret_cast<const float4*>(g_P + ((size_t)(0 * NSPLIT_TILES + t) << 14)) + e);
    const float4 b = *(reinterpret_cast<const float4*>(g_P + ((size_t)(1 * NSPLIT_TILES + t) << 14)) + e);
    const float4 c = *(reinterpret_cast<const float4*>(g_P + ((size_t)(2 * NSPLIT_TILES + t) << 14)) + e);
    const float4 d = *(reinterpret_cast<const float4*>(g_P + ((size_t)(3 * NSPLIT_TILES + t) << 14)) + e);
    const float4 bv = __ldg(reinterpret_cast<const float4*>(bias) + tn / 4 + c4);
    float4 r;
    r.x = (a.x + b.x) + (c.x + d.x) + bv.x;
    r.y = (a.y + b.y) + (c.y + d.y) + bv.y;
    r.z = (a.z + b.z) + (c.z + d.z) + bv.z;
    r.w = (a.w + b.w) + (c.w + d.w) + bv.w;
    reinterpret_cast<float4*>(out)[(size_t)row * (N_DIM / 4) + tn / 4 + c4] = r;
}

__global__ void __launch_bounds__(160, 2)
gemm_k(const __grid_constant__ CUtensorMap tma_a,
       const __grid_constant__ CUtensorMap tma_b,
       const float* __restrict__ bias, float* __restrict__ out) {
    extern __shared__ char dsm[];
    __shared__ uint64_t bars[2 * NSTAGES];

    const uint32_t tiles_s = (smem_u32(dsm) + 1023u) & ~1023u;
    const uint32_t bar0 = smem_u32(bars);
    const int tid = threadIdx.x;
    const int wid = tid >> 5;
    const int lane = tid & 31;
    const int bx = blockIdx.x;
    const int nq = (bx < NQTASK - 2 * NCTA) ? 3 : 2;   // bx<272 -> 3 : 2
    const int ntask = nq + 1;

    if (tid == 0) {
        #pragma unroll
        for (int s = 0; s < NSTAGES; s++) {
            MBAR_INIT(bar0 + s * 8, 1);               // full: tx-based
            MBAR_INIT(bar0 + (NSTAGES + s) * 8, 4);   // empty: 4 MMA warps
        }
    }
    __syncthreads();

    if (wid == 4) {
        // =============== producer warp: pure TMA (lane 0) ===============
        if (lane == 0) {
            int g = 0;
            for (int tt = 0; tt < ntask; tt++) {
                int tm, tn, kb, nch, j;
                task_decode(bx, nq, tt, tm, tn, kb, nch, j);
                for (int t = 0; t < nch; t++, g++) {
                    const int s = g % NSTAGES;
                    if (g >= NSTAGES)
                        MBAR_WAIT(bar0 + (NSTAGES + s) * 8, ((g / NSTAGES) - 1) & 1);
                    MBAR_EXPECT_TX(bar0 + s * 8, STAGE_BYTES);
                    const uint32_t st = tiles_s + s * STAGE_BYTES;
                    const int cx = (kb + t) * BK;
                    TMA_LOAD_3D(st,           &tma_a, cx, tm, 0, bar0 + s * 8);
                    TMA_LOAD_3D(st + A_BYTES, &tma_b, cx, tn, 0, bar0 + s * 8);
                }
            }
        }
    } else {
        // =============== MMA warps (0..3), warp tile 64x64 ===============
        const int wm = (wid & 1) * 64;
        const int wn = (wid >> 1) * 64;

        const int a_row_l = (lane & 15);
        const int a_k16   = (lane >> 4) * 16;
        const int b_row_l = (lane & 7) + ((lane >> 4) << 3);
        const int b_k16   = ((lane >> 3) & 1) * 16;

        uint32_t a_base[4], a_xor[4];
        #pragma unroll
        for (int fm = 0; fm < 4; fm++) {
            const int r = wm + fm * 16 + a_row_l;
            a_base[fm] = r * 128;
            a_xor[fm] = (r & 7) << 4;
        }
        uint32_t b_base[4], b_xor[4];
        #pragma unroll
        for (int fn = 0; fn < 4; fn++) {
            const int r = wn + fn * 16 + b_row_l;
            b_base[fn] = r * 128;
            b_xor[fn] = (r & 7) << 4;
        }

        int g = 0;
        for (int tt = 0; tt < ntask; tt++) {
            int tm, tn, kb, nch, j;
            task_decode(bx, nq, tt, tm, tn, kb, nch, j);

            float acc[4][8][4];
            #pragma unroll
            for (int i = 0; i < 4; i++)
                #pragma unroll
                for (int jj = 0; jj < 8; jj++)
                    #pragma unroll
                    for (int c = 0; c < 4; c++) acc[i][jj][c] = 0.f;

            for (int t = 0; t < nch; t++, g++) {
                const int s = g % NSTAGES;
                MBAR_WAIT(bar0 + s * 8, (g / NSTAGES) & 1);
                const uint32_t sa = tiles_s + s * STAGE_BYTES;
                const uint32_t sb = sa + A_BYTES;

                #pragma unroll
                for (int ks = 0; ks < 4; ks++) {
                    uint32_t af[4][4], bf[4][4];
                    #pragma unroll
                    for (int fm = 0; fm < 4; fm++)
                        ldsm_x4(af[fm], sa + a_base[fm] + ((ks * 32 + a_k16) ^ a_xor[fm]));
                    #pragma unroll
                    for (int fn = 0; fn < 4; fn++)
                        ldsm_x4(bf[fn], sb + b_base[fn] + ((ks * 32 + b_k16) ^ b_xor[fn]));
                    #pragma unroll
                    for (int fm = 0; fm < 4; fm++)
                        #pragma unroll
                        for (int fn = 0; fn < 4; fn++) {
                            mma16816(acc[fm][2 * fn],     af[fm], bf[fn][0], bf[fn][1]);
                            mma16816(acc[fm][2 * fn + 1], af[fm], bf[fn][2], bf[fn][3]);
                        }
                }
                __syncwarp();
                if (lane == 0) MBAR_ARRIVE(bar0 + (NSTAGES + s) * 8);
            }

            // ---- epilogue ----
            const int gid4 = lane >> 2;
            const int tig  = lane & 3;
            if (j < 0) {
                #pragma unroll
                for (int fm = 0; fm < 4; fm++) {
                    const int row = tm + wm + fm * 16 + gid4;
                    #pragma unroll
                    for (int fn = 0; fn < 8; fn++) {
                        const int col = tn + wn + fn * 8 + tig * 2;
                        const float b0 = __ldg(&bias[col]);
                        const float b1 = __ldg(&bias[col + 1]);
                        float2 v0 = make_float2(acc[fm][fn][0] + b0, acc[fm][fn][1] + b1);
                        float2 v1 = make_float2(acc[fm][fn][2] + b0, acc[fm][fn][3] + b1);
                        *reinterpret_cast<float2*>(out + (size_t)row * N_DIM + col)       = v0;
                        *reinterpret_cast<float2*>(out + (size_t)(row + 8) * N_DIM + col) = v1;
                    }
                }
            } else {
                // quarter-K partial: plain STG + per-thread counter release
                float* base = g_P + (size_t)j * 16384;
                #pragma unroll
                for (int fm = 0; fm < 4; fm++) {
                    const int rl2 = wm + fm * 16 + gid4;
                    #pragma unroll
                    for (int fn = 0; fn < 8; fn++) {
                        const int cl = wn + fn * 8 + tig * 2;
                        *reinterpret_cast<float2*>(base + rl2 * 128 + cl) =
                            make_float2(acc[fm][fn][0], acc[fm][fn][1]);
                        *reinterpret_cast<float2*>(base + (rl2 + 8) * 128 + cl) =
                            make_float2(acc[fm][fn][2], acc[fm][fn][3]);
                    }
                }
                asm volatile("red.release.gpu.global.add.u32 [%0], %1;"
                             :: "l"(g_qcnt + (j % NSPLIT_TILES) * 64 + lane), "r"(1u)
                             : "memory");
            }
        }
    }

    // ================= TAIL: split-K reduce (all 160 threads) =================
    int start4, end4;
    if (bx >= NCTA - NFAST) {
        const int t0 = FAST_T0 + (bx - (NCTA - NFAST)) * 2;   // 2 whole tiles
        start4 = t0 << 12;
        end4 = start4 + (2 << 12);
    } else {
        start4 = bx * SLOW_F4;
        int lim = FAST_T0 << 12;                               // 688128
        end4 = start4 + SLOW_F4;
        if (end4 > lim) end4 = lim;
    }
    if (start4 < end4) {
        const int tA = start4 >> 12;
        const int tB = (end4 - 1) >> 12;
        if (wid == 0) {
            for (int t = tA; t <= tB; t++) {
                uint32_t v; int ok;
                do {
                    asm volatile("ld.acquire.gpu.global.u32 %0, [%1];"
                                 : "=r"(v) : "l"(g_qcnt + t * 64 + lane) : "memory");
                    ok = (v >= 16);
                    if (!__all_sync(0xffffffffu, ok))
                        asm volatile("nanosleep.u32 128;");
                    else break;
                } while (true);
            }
            __syncwarp();
        }
    }
    __syncthreads();   // broadcast acquired visibility to all 160 threads
    for (int u = start4 + tid; u < end4; u += 160)
        reduce_elem(u, bias, out);
}

// ---------------------------------------------------------------------------
typedef CUresult (*tmap_fn)(CUtensorMap*, CUtensorMapDataType, cuuint32_t, void*,
                            const cuuint64_t*, const cuuint64_t*, const cuuint32_t*,
                            const cuuint32_t*, CUtensorMapInterleave, CUtensorMapSwizzle,
                            CUtensorMapL2promotion, CUtensorMapFloatOOBfill);

static void make_map(tmap_fn enc, CUtensorMap* m, void* base, uint64_t rows) {
    cuuint64_t dims[3]    = {K_DIM, rows, 1};
    cuuint64_t strides[2] = {K_DIM * 2ull, rows * K_DIM * 2ull};
    cuuint32_t box[3]     = {64, 128, 1};    // 64 halves = 128B row (SW128)
    cuuint32_t es[3]      = {1, 1, 1};
    enc(m, CU_TENSOR_MAP_DATA_TYPE_FLOAT16, 3, base, dims, strides, box, es,
        CU_TENSOR_MAP_INTERLEAVE_NONE, CU_TENSOR_MAP_SWIZZLE_128B,
        CU_TENSOR_MAP_L2_PROMOTION_L2_128B, CU_TENSOR_MAP_FLOAT_OOB_FILL_NONE);
}

extern "C" void kernel_launch(void* const* d_in, const int* in_sizes, int n_in,
                              void* d_out, int out_size) {
    const float* x    = (const float*)d_in[0];   // [2048, 4096]
    const float* seed = (const float*)d_in[1];   // [4096, 4096]
    const float* da   = (const float*)d_in[2];   // [20]
    const float* db   = (const float*)d_in[3];   // [20]
    const float* bias = (const float*)d_in[4];   // [4096]
    float* out = (float*)d_out;                  // [2048, 4096]
    const int niter = in_sizes[2];

    void* pW = nullptr; void* pX = nullptr;
    cudaGetSymbolAddress(&pW, g_Wh);
    cudaGetSymbolAddress(&pX, g_Xh);

    tmap_fn enc = nullptr;
    cudaDriverEntryPointQueryResult qr;
    cudaGetDriverEntryPointByVersion("cuTensorMapEncodeTiled", (void**)&enc, 12000,
                                     cudaEnableDefault, &qr);

    CUtensorMap map_a, map_b;
    make_map(enc, &map_a, pX, M_DIM);   // A = X
    make_map(enc, &map_b, pW, N_DIM);   // B = W

    prep_k<<<PREP_BLOCKS, 256>>>(x, seed, da, db, niter);

    cudaFuncSetAttribute(gemm_k, cudaFuncAttributeMaxDynamicSharedMemorySize, DYN_SMEM);
    gemm_k<<<NCTA, 160, DYN_SMEM>>>(map_a, map_b, bias, out);
}

// round 17
// speedup vs baseline: 1.1619x; 1.1002x over previous
#include <cuda.h>
#include <cuda_runtime.h>
#include <cuda_fp16.h>
#include <cstdint>

#define M_DIM 2048
#define N_DIM 4096
#define K_DIM 4096

// ---------------- scratch (static device globals; no runtime alloc) -------
__device__ __half g_Wh[(size_t)N_DIM * K_DIM];   // transcribed weight, fp16
__device__ __half g_Xh[(size_t)M_DIM * K_DIM];   // x, fp16
// split-K partials, fp16: 864 quarter tasks x (128x128) = 28.3MB
#define NSPLIT_TILES 216
#define NQTASK 864
__device__ __half g_P[(size_t)NQTASK * 16384];

// ---------------- PTX helpers ----------------------------------------------
__device__ __forceinline__ uint32_t smem_u32(const void* p) {
    uint32_t a;
    asm("{ .reg .u64 t; cvta.to.shared.u64 t, %1; cvt.u32.u64 %0, t; }" : "=r"(a) : "l"(p));
    return a;
}
#define MBAR_INIT(a, n) \
    asm volatile("mbarrier.init.shared.b64 [%0], %1;" :: "r"(a), "r"((uint32_t)(n)) : "memory")
#define MBAR_EXPECT_TX(a, b) \
    asm volatile("mbarrier.arrive.expect_tx.shared.b64 _, [%0], %1;" :: "r"(a), "r"((uint32_t)(b)) : "memory")
#define MBAR_ARRIVE(a) \
    asm volatile("mbarrier.arrive.shared.b64 _, [%0];" :: "r"(a) : "memory")
#define MBAR_WAIT(a, ph) do {                                                   \
    uint32_t _m = (a); uint32_t _p = (ph); uint32_t _d;                         \
    asm volatile("{\n\t.reg .pred p;\n\t"                                       \
        "mbarrier.try_wait.parity.acquire.cta.shared::cta.b64 p, [%1], %2;\n\t" \
        "selp.b32 %0, 1, 0, p;\n\t}"                                            \
        : "=r"(_d) : "r"(_m), "r"(_p) : "memory");                              \
    if (!_d) {                                                                  \
        asm volatile("{\n\t.reg .pred P1;\n\t"                                  \
            "WL_%=:\n\t"                                                        \
            "mbarrier.try_wait.parity.acquire.cta.shared::cta.b64 P1, [%0], %1, 0x989680;\n\t" \
            "@P1 bra.uni WD_%=;\n\t"                                            \
            "bra.uni WL_%=;\n\t"                                                \
            "WD_%=:\n\t}" :: "r"(_m), "r"(_p) : "memory");                      \
    } } while (0)
#define TMA_LOAD_3D(smem_addr, map, cx, cy, cz, bar)                            \
    asm volatile("cp.async.bulk.tensor.3d.shared::cta.global.tile"              \
        ".mbarrier::complete_tx::bytes "                                        \
        "[%0], [%1, {%2, %3, %4}], [%5];"                                       \
        :: "r"((uint32_t)(smem_addr)), "l"(map),                                \
           "r"((int32_t)(cx)), "r"((int32_t)(cy)), "r"((int32_t)(cz)),          \
           "r"((uint32_t)(bar)) : "memory")

__device__ __forceinline__ void ldsm_x4(uint32_t (&r)[4], uint32_t addr) {
    asm volatile("ldmatrix.sync.aligned.m8n8.x4.shared.b16 {%0,%1,%2,%3}, [%4];"
        : "=r"(r[0]), "=r"(r[1]), "=r"(r[2]), "=r"(r[3]) : "r"(addr));
}
__device__ __forceinline__ void mma16816(float (&d)[4], const uint32_t (&a)[4],
                                         uint32_t b0, uint32_t b1) {
    asm volatile("mma.sync.aligned.m16n8k16.row.col.f32.f16.f16.f32 "
        "{%0,%1,%2,%3},{%4,%5,%6,%7},{%8,%9},{%0,%1,%2,%3};"
        : "+f"(d[0]), "+f"(d[1]), "+f"(d[2]), "+f"(d[3])
        : "r"(a[0]), "r"(a[1]), "r"(a[2]), "r"(a[3]), "r"(b0), "r"(b1));
}

// FMA-pipe-only sin (validated R14): magic-number pi reduction + odd Taylor.
#define SIN_MAGIC 12582912.0f
#define SIN_INVPI 0.318309886f
#define SIN_PIHI  3.14159274f
#define SIN_PILO  -8.742278e-8f
__device__ __forceinline__ float sin_poly(float x) {
    const float t  = fmaf(x, SIN_INVPI, SIN_MAGIC);
    const int  par = (__float_as_int(t) & 1) << 31;
    const float nf = t - SIN_MAGIC;
    float y = fmaf(nf, -SIN_PIHI, x);
    y = fmaf(nf, -SIN_PILO, y);
    const float z = y * y;
    float r = fmaf(2.75573192e-6f, z, -1.98412698e-4f);
    r = fmaf(r, z, 8.33333333e-3f);
    r = fmaf(r, z, -1.66666667e-1f);
    const float s = fmaf(y * z, r, y);
    return __int_as_float(__float_as_int(s) ^ par);
}

// ---------------------------------------------------------------------------
// Kernel 1: fractal transcription of W (fp16) + fp16 round of X.
//   8 elems/thread; elem 0 via FMA-pipe poly sin, elems 1..7 via MUFU __sinf.
//   (validated R14: 70.3us, 98.5% of hybrid MUFU floor)
// ---------------------------------------------------------------------------
#define NW8 ((size_t)N_DIM * K_DIM / 8)           // 2,097,152 threads
#define NX8 ((size_t)M_DIM * K_DIM / 8)           // 1,048,576 threads
#define PREP_BLOCKS ((unsigned)((NW8 + NX8) / 256))   // 12288 exactly

__global__ void prep_k(const float* __restrict__ x, const float* __restrict__ seed,
                       const float* __restrict__ da, const float* __restrict__ db,
                       int niter) {
    __shared__ float sa[32], sb[32];
    if (threadIdx.x < 32 && threadIdx.x < niter) {
        sa[threadIdx.x] = da[threadIdx.x];
        sb[threadIdx.x] = db[threadIdx.x];
    }
    __syncthreads();

    size_t gid = (size_t)blockIdx.x * blockDim.x + threadIdx.x;
    if (gid < NW8) {
        size_t i = gid * 8;
        float4 w0 = *reinterpret_cast<const float4*>(seed + i);
        float4 w1 = *reinterpret_cast<const float4*>(seed + i + 4);
        float v0 = w0.x, v1 = w0.y, v2 = w0.z, v3 = w0.w;
        float v4 = w1.x, v5 = w1.y, v6 = w1.z, v7 = w1.w;
        #pragma unroll 20
        for (int k = 0; k < niter; k++) {
            const float a = sa[k], b = sb[k];
            v0 = fmaf(b, sin_poly(v0), a * v0);    // FMA pipe
            v1 = fmaf(b, __sinf(v1), a * v1);      // MUFU
            v2 = fmaf(b, __sinf(v2), a * v2);
            v3 = fmaf(b, __sinf(v3), a * v3);
            v4 = fmaf(b, __sinf(v4), a * v4);
            v5 = fmaf(b, __sinf(v5), a * v5);
            v6 = fmaf(b, __sinf(v6), a * v6);
            v7 = fmaf(b, __sinf(v7), a * v7);
        }
        __half2 h0 = __floats2half2_rn(v0, v1);
        __half2 h1 = __floats2half2_rn(v2, v3);
        __half2 h2 = __floats2half2_rn(v4, v5);
        __half2 h3 = __floats2half2_rn(v6, v7);
        uint4 o = make_uint4(*(uint32_t*)&h0, *(uint32_t*)&h1,
                             *(uint32_t*)&h2, *(uint32_t*)&h3);
        *reinterpret_cast<uint4*>(g_Wh + i) = o;
    } else {
        size_t i = (gid - NW8) * 8;
        float4 a0 = *reinterpret_cast<const float4*>(x + i);
        float4 a1 = *reinterpret_cast<const float4*>(x + i + 4);
        __half2 h0 = __floats2half2_rn(a0.x, a0.y);
        __half2 h1 = __floats2half2_rn(a0.z, a0.w);
        __half2 h2 = __floats2half2_rn(a1.x, a1.y);
        __half2 h3 = __floats2half2_rn(a1.z, a1.w);
        uint4 o = make_uint4(*(uint32_t*)&h0, *(uint32_t*)&h1,
                             *(uint32_t*)&h2, *(uint32_t*)&h3);
        *reinterpret_cast<uint4*>(g_Xh + i) = o;
    }
}

// ---------------------------------------------------------------------------
// Kernel 2: persistent GEMM (validated R13/R14 engine, ~149us).
//   296 CTAs x 160 threads, 2 CTAs/SM, 128x128 tile, 4 MMA warps (64x64) +
//   1 TMA producer, NSTAGES=3. Full-K tile FIRST, then quarter-K tasks
//   (fp16 partials into g_P, combined by reduce_k).
// ---------------------------------------------------------------------------
#define NSTAGES 3
#define BK      64
#define A_BYTES (128 * 128)                  // 16KB
#define STAGE_BYTES (2 * A_BYTES)            // 32KB
#define DYN_SMEM (NSTAGES * STAGE_BYTES + 1024)   // 99328B -> 2 CTAs/SM
#define NCTA    296

__device__ __forceinline__ void task_decode(int bx, int tt, int& tm, int& tn,
                                            int& kb, int& nch, int& j) {
    if (tt == 0) {
        tm = (bx & 15) << 7;
        tn = (bx >> 4) << 7;
        kb = 0; nch = 64; j = -1;
    } else {
        j = bx + (tt - 1) * NCTA;                  // 0..863
        const int tile = NCTA + (j % NSPLIT_TILES);
        tm = (tile & 15) << 7;
        tn = (tile >> 4) << 7;
        kb = (j / NSPLIT_TILES) * 16;              // k-quarter
        nch = 16;
    }
}

__global__ void __launch_bounds__(160, 2)
gemm_k(const __grid_constant__ CUtensorMap tma_a,
       const __grid_constant__ CUtensorMap tma_b,
       const float* __restrict__ bias, float* __restrict__ out) {
    extern __shared__ char dsm[];
    __shared__ uint64_t bars[2 * NSTAGES];

    const uint32_t tiles_s = (smem_u32(dsm) + 1023u) & ~1023u;
    const uint32_t bar0 = smem_u32(bars);
    const int tid = threadIdx.x;
    const int wid = tid >> 5;
    const int lane = tid & 31;
    const int bx = blockIdx.x;
    const int ntask = 1 + ((bx < NQTASK - 2 * NCTA) ? 3 : 2);   // bx<272 -> 4 : 3

    if (tid == 0) {
        #pragma unroll
        for (int s = 0; s < NSTAGES; s++) {
            MBAR_INIT(bar0 + s * 8, 1);               // full: tx-based
            MBAR_INIT(bar0 + (NSTAGES + s) * 8, 4);   // empty: 4 MMA warps
        }
    }
    __syncthreads();

    // ===================== producer warp (4): pure TMA, lane 0 ==========
    if (wid == 4) {
        if (lane == 0) {
            int g = 0;
            for (int tt = 0; tt < ntask; tt++) {
                int tm, tn, kb, nch, j;
                task_decode(bx, tt, tm, tn, kb, nch, j);
                for (int t = 0; t < nch; t++, g++) {
                    const int s = g % NSTAGES;
                    if (g >= NSTAGES)
                        MBAR_WAIT(bar0 + (NSTAGES + s) * 8, ((g / NSTAGES) - 1) & 1);
                    MBAR_EXPECT_TX(bar0 + s * 8, STAGE_BYTES);
                    const uint32_t st = tiles_s + s * STAGE_BYTES;
                    const int cx = (kb + t) * BK;
                    TMA_LOAD_3D(st,           &tma_a, cx, tm, 0, bar0 + s * 8);
                    TMA_LOAD_3D(st + A_BYTES, &tma_b, cx, tn, 0, bar0 + s * 8);
                }
            }
        }
        return;
    }

    // ===================== MMA warps (0..3), warp tile 64x64 =====
    const int wm = (wid & 1) * 64;       // {0,64}
    const int wn = (wid >> 1) * 64;      // {0,64}

    const int a_row_l = (lane & 15);
    const int a_k16   = (lane >> 4) * 16;
    const int b_row_l = (lane & 7) + ((lane >> 4) << 3);
    const int b_k16   = ((lane >> 3) & 1) * 16;

    uint32_t a_base[4], a_xor[4];
    #pragma unroll
    for (int fm = 0; fm < 4; fm++) {
        const int r = wm + fm * 16 + a_row_l;
        a_base[fm] = r * 128;
        a_xor[fm] = (r & 7) << 4;
    }
    uint32_t b_base[4], b_xor[4];
    #pragma unroll
    for (int fn = 0; fn < 4; fn++) {
        const int r = wn + fn * 16 + b_row_l;
        b_base[fn] = r * 128;
        b_xor[fn] = (r & 7) << 4;
    }

    int g = 0;
    for (int tt = 0; tt < ntask; tt++) {
        int tm, tn, kb, nch, j;
        task_decode(bx, tt, tm, tn, kb, nch, j);

        float acc[4][8][4];
        #pragma unroll
        for (int i = 0; i < 4; i++)
            #pragma unroll
            for (int jj = 0; jj < 8; jj++)
                #pragma unroll
                for (int c = 0; c < 4; c++) acc[i][jj][c] = 0.f;

        for (int t = 0; t < nch; t++, g++) {
            const int s = g % NSTAGES;
            MBAR_WAIT(bar0 + s * 8, (g / NSTAGES) & 1);
            const uint32_t sa = tiles_s + s * STAGE_BYTES;
            const uint32_t sb = sa + A_BYTES;

            #pragma unroll
            for (int ks = 0; ks < 4; ks++) {
                uint32_t af[4][4], bf[4][4];
                #pragma unroll
                for (int fm = 0; fm < 4; fm++)
                    ldsm_x4(af[fm], sa + a_base[fm] + ((ks * 32 + a_k16) ^ a_xor[fm]));
                #pragma unroll
                for (int fn = 0; fn < 4; fn++)
                    ldsm_x4(bf[fn], sb + b_base[fn] + ((ks * 32 + b_k16) ^ b_xor[fn]));
                #pragma unroll
                for (int fm = 0; fm < 4; fm++)
                    #pragma unroll
                    for (int fn = 0; fn < 4; fn++) {
                        mma16816(acc[fm][2 * fn],     af[fm], bf[fn][0], bf[fn][1]);
                        mma16816(acc[fm][2 * fn + 1], af[fm], bf[fn][2], bf[fn][3]);
                    }
            }
            __syncwarp();
            if (lane == 0) MBAR_ARRIVE(bar0 + (NSTAGES + s) * 8);
        }

        // ---- epilogue ----
        const int gid4 = lane >> 2;
        const int tig  = lane & 3;
        if (j < 0) {
            #pragma unroll
            for (int fm = 0; fm < 4; fm++) {
                const int row = tm + wm + fm * 16 + gid4;
                #pragma unroll
                for (int fn = 0; fn < 8; fn++) {
                    const int col = tn + wn + fn * 8 + tig * 2;
                    const float b0 = __ldg(&bias[col]);
                    const float b1 = __ldg(&bias[col + 1]);
                    float2 v0 = make_float2(acc[fm][fn][0] + b0, acc[fm][fn][1] + b1);
                    float2 v1 = make_float2(acc[fm][fn][2] + b0, acc[fm][fn][3] + b1);
                    *reinterpret_cast<float2*>(out + (size_t)row * N_DIM + col)       = v0;
                    *reinterpret_cast<float2*>(out + (size_t)(row + 8) * N_DIM + col) = v1;
                }
            }
        } else {
            // quarter-K partial: fp16 STG into scratch (half the bytes)
            __half* base = g_P + (size_t)j * 16384;
            #pragma unroll
            for (int fm = 0; fm < 4; fm++) {
                const int rl2 = wm + fm * 16 + gid4;
                #pragma unroll
                for (int fn = 0; fn < 8; fn++) {
                    const int cl = wn + fn * 8 + tig * 2;
                    __half2 p0 = __floats2half2_rn(acc[fm][fn][0], acc[fm][fn][1]);
                    __half2 p1 = __floats2half2_rn(acc[fm][fn][2], acc[fm][fn][3]);
                    *reinterpret_cast<__half2*>(base + rl2 * 128 + cl)       = p0;
                    *reinterpret_cast<__half2*>(base + (rl2 + 8) * 128 + cl) = p1;
                }
            }
        }
    }
}

// ---------------------------------------------------------------------------
// Kernel 3: combine fp16 quarter partials: out = bias + sum(q)
//   216 tiles x 4096 float4 = 884736 threads -> 3456 blocks x 256.
// ---------------------------------------------------------------------------
__global__ void reduce_k(const float* __restrict__ bias, float* __restrict__ out) {
    const size_t gid = (size_t)blockIdx.x * blockDim.x + threadIdx.x;   // < 884736
    const int t = (int)(gid >> 12);          // split tile 0..215
    const int e = (int)(gid & 4095);         // float4 (= 4 halves/quarter)
    const int tile = NCTA + t;
    const int tm = (tile & 15) << 7;
    const int tn = (tile >> 4) << 7;
    const int row = tm + (e >> 5);
    const int c4 = e & 31;

    float4 s = make_float4(0.f, 0.f, 0.f, 0.f);
    #pragma unroll
    for (int q = 0; q < 4; q++) {
        const __half* p = g_P + ((size_t)(q * NSPLIT_TILES + t) << 14) + e * 4;
        const uint2 u = *reinterpret_cast<const uint2*>(p);
        const float2 lo = __half22float2(*reinterpret_cast<const __half2*>(&u.x));
        const float2 hi = __half22float2(*reinterpret_cast<const __half2*>(&u.y));
        s.x += lo.x; s.y += lo.y; s.z += hi.x; s.w += hi.y;
    }
    const float4 bv = __ldg(reinterpret_cast<const float4*>(bias) + tn / 4 + c4);
    float4 r;
    r.x = s.x + bv.x;
    r.y = s.y + bv.y;
    r.z = s.z + bv.z;
    r.w = s.w + bv.w;
    reinterpret_cast<float4*>(out)[(size_t)row * (N_DIM / 4) + tn / 4 + c4] = r;
}

// ---------------------------------------------------------------------------
typedef CUresult (*tmap_fn)(CUtensorMap*, CUtensorMapDataType, cuuint32_t, void*,
                            const cuuint64_t*, const cuuint64_t*, const cuuint32_t*,
                            const cuuint32_t*, CUtensorMapInterleave, CUtensorMapSwizzle,
                            CUtensorMapL2promotion, CUtensorMapFloatOOBfill);

static void make_map(tmap_fn enc, CUtensorMap* m, void* base, uint64_t rows) {
    cuuint64_t dims[3]    = {K_DIM, rows, 1};
    cuuint64_t strides[2] = {K_DIM * 2ull, rows * K_DIM * 2ull};
    cuuint32_t box[3]     = {64, 128, 1};    // 64 halves = 128B row (SW128)
    cuuint32_t es[3]      = {1, 1, 1};
    enc(m, CU_TENSOR_MAP_DATA_TYPE_FLOAT16, 3, base, dims, strides, box, es,
        CU_TENSOR_MAP_INTERLEAVE_NONE, CU_TENSOR_MAP_SWIZZLE_128B,
        CU_TENSOR_MAP_L2_PROMOTION_L2_128B, CU_TENSOR_MAP_FLOAT_OOB_FILL_NONE);
}

extern "C" void kernel_launch(void* const* d_in, const int* in_sizes, int n_in,
                              void* d_out, int out_size) {
    const float* x    = (const float*)d_in[0];   // [2048, 4096]
    const float* seed = (const float*)d_in[1];   // [4096, 4096]
    const float* da   = (const float*)d_in[2];   // [20]
    const float* db   = (const float*)d_in[3];   // [20]
    const float* bias = (const float*)d_in[4];   // [4096]
    float* out = (float*)d_out;                  // [2048, 4096]
    const int niter = in_sizes[2];

    void* pW = nullptr; void* pX = nullptr;
    cudaGetSymbolAddress(&pW, g_Wh);
    cudaGetSymbolAddress(&pX, g_Xh);

    tmap_fn enc = nullptr;
    cudaDriverEntryPointQueryResult qr;
    cudaGetDriverEntryPointByVersion("cuTensorMapEncodeTiled", (void**)&enc, 12000,
                                     cudaEnableDefault, &qr);

    CUtensorMap map_a, map_b;
    make_map(enc, &map_a, pX, M_DIM);   // A = X
    make_map(enc, &map_b, pW, N_DIM);   // B = W

    prep_k<<<PREP_BLOCKS, 256>>>(x, seed, da, db, niter);

    cudaFuncSetAttribute(gemm_k, cudaFuncAttributeMaxDynamicSharedMemorySize, DYN_SMEM);
    gemm_k<<<NCTA, 160, DYN_SMEM>>>(map_a, map_b, bias, out);

    reduce_k<<<3456, 256>>>(bias, out);
}